// round 11
// baseline (speedup 1.0000x reference)
#include <cuda_runtime.h>
#include <cuda_bf16.h>
#include <cstdint>

#define Bq 2
#define Tq 2048
#define Dq 1024
#define VDq 2048
#define FFq 2752
#define FFp 5632
#define Hq 16
#define DKq 64
#define DVq 128
#define Mq (Bq*Tq)      // 4096

// ---------------- device scratch --------------------------------------------
__device__ float g_qkvg[Mq*(size_t)6144];
__device__ float g_q   [Mq*(size_t)Dq];
__device__ float g_k   [Mq*(size_t)Dq];
__device__ float g_v   [Mq*(size_t)VDq];
__device__ float g_bt  [Mq*(size_t)Hq];
__device__ float g_gd  [Mq*(size_t)Hq];     // exp(g) decay
__device__ float g_o   [Mq*(size_t)VDq];
__device__ float g_x   [Mq*(size_t)Dq];
__device__ float g_gu  [Mq*(size_t)FFp];
__device__ __nv_bfloat16 g_Aexp [Mq*(size_t)5504];      // [Ah|Al], max width 2*2752
__device__ __nv_bfloat16 g_Bqkvg[(size_t)6144*2048];    // [Bh|Bl] per row
__device__ __nv_bfloat16 g_Bo   [(size_t)1024*4096];
__device__ __nv_bfloat16 g_Bmlp [(size_t)FFp*2048];
__device__ __nv_bfloat16 g_Bdwn [(size_t)1024*5504];

// ---------------- PTX helpers ------------------------------------------------
__device__ __forceinline__ uint32_t smem_u32(const void* p) {
    uint32_t a;
    asm("{ .reg .u64 t; cvta.to.shared.u64 t, %1; cvt.u32.u64 %0, t; }" : "=r"(a) : "l"(p));
    return a;
}
typedef unsigned long long ull;
__device__ __forceinline__ ull ffma2(ull a, ull b, ull c) {
    ull d; asm("fma.rn.f32x2 %0,%1,%2,%3;" : "=l"(d) : "l"(a), "l"(b), "l"(c)); return d;
}
__device__ __forceinline__ ull mul2(ull a, ull b) {
    ull d; asm("mul.rn.f32x2 %0,%1,%2;" : "=l"(d) : "l"(a), "l"(b)); return d;
}
__device__ __forceinline__ ull dup2(float x) {
    ull r; asm("mov.b64 %0, {%1,%1};" : "=l"(r) : "f"(x)); return r;
}
__device__ __forceinline__ float2 unpk(ull a) {
    float2 f; asm("mov.b64 {%0,%1}, %2;" : "=f"(f.x), "=f"(f.y) : "l"(a)); return f;
}
__device__ __forceinline__ float siluf(float x) { return x / (1.0f + __expf(-x)); }

__device__ __forceinline__ void split4(float4 v, ull& hi, ull& lo) {
    __nv_bfloat16 h0 = __float2bfloat16(v.x), h1 = __float2bfloat16(v.y),
                  h2 = __float2bfloat16(v.z), h3 = __float2bfloat16(v.w);
    __nv_bfloat16 l0 = __float2bfloat16(v.x - __bfloat162float(h0));
    __nv_bfloat16 l1 = __float2bfloat16(v.y - __bfloat162float(h1));
    __nv_bfloat16 l2 = __float2bfloat16(v.z - __bfloat162float(h2));
    __nv_bfloat16 l3 = __float2bfloat16(v.w - __bfloat162float(h3));
    ushort4 hu = make_ushort4(__bfloat16_as_ushort(h0), __bfloat16_as_ushort(h1),
                              __bfloat16_as_ushort(h2), __bfloat16_as_ushort(h3));
    ushort4 lu = make_ushort4(__bfloat16_as_ushort(l0), __bfloat16_as_ushort(l1),
                              __bfloat16_as_ushort(l2), __bfloat16_as_ushort(l3));
    hi = *(ull*)&hu; lo = *(ull*)&lu;
}

#define SWZ(o) ((o) ^ (((o) >> 3) & 0x70))
#define CP16(d, s) asm volatile("cp.async.cg.shared.global [%0], [%1], 16;" :: "r"(d), "l"(s) : "memory")
#define CP4(d, s)  asm volatile("cp.async.ca.shared.global [%0], [%1], 4;"  :: "r"(d), "l"(s) : "memory")
#define CPCOMMIT() asm volatile("cp.async.commit_group;" ::: "memory")
#define CPWAIT1()  asm volatile("cp.async.wait_group 1;" ::: "memory")

#define LDMX4(r0,r1,r2,r3,addr) \
    asm volatile("ldmatrix.sync.aligned.m8n8.x4.shared.b16 {%0,%1,%2,%3}, [%4];" \
                 : "=r"(r0), "=r"(r1), "=r"(r2), "=r"(r3) : "r"(addr))

#define MMA16816(c, a, b) \
    asm volatile("mma.sync.aligned.m16n8k16.row.col.f32.bf16.bf16.f32 " \
                 "{%0,%1,%2,%3}, {%4,%5,%6,%7}, {%8,%9}, {%0,%1,%2,%3};" \
                 : "+f"((c)[0]), "+f"((c)[1]), "+f"((c)[2]), "+f"((c)[3]) \
                 : "r"((a)[0]), "r"((a)[1]), "r"((a)[2]), "r"((a)[3]), \
                   "r"((b)[0]), "r"((b)[1]))

// ---------------- combined weight split/transpose (one launch) ---------------
struct SJobs {
    const float* src[8];
    __nv_bfloat16* dst[8];
    int K[8], N[8], nx[8], blocks[8];
};

__global__ void splitT_all(SJobs jb) {
    __shared__ float tile[32][33];
    int bx = blockIdx.x, j = 0, base = 0;
    for (j = 0; j < 8; j++) {
        if (bx < base + jb.blocks[j]) break;
        base += jb.blocks[j];
    }
    int local = bx - base;
    int K = jb.K[j], N = jb.N[j];
    const float* W = jb.src[j];
    __nv_bfloat16* out = jb.dst[j];
    int n0 = (local % jb.nx[j]) * 32;
    int k0 = (local / jb.nx[j]) * 32;

    for (int r = threadIdx.y; r < 32; r += 8)
        tile[r][threadIdx.x] = W[(size_t)(k0 + r) * N + n0 + threadIdx.x];
    __syncthreads();
    for (int r = threadIdx.y; r < 32; r += 8) {
        int n = n0 + r, kk = k0 + threadIdx.x;
        float x = tile[threadIdx.x][r];
        __nv_bfloat16 hi = __float2bfloat16(x);
        __nv_bfloat16 lo = __float2bfloat16(x - __bfloat162float(hi));
        __nv_bfloat16* orow = out + (size_t)n * (2 * K);
        orow[kk] = hi; orow[K + kk] = lo;   // [Bh|Bl]
    }
}

__global__ void act_split(const float* __restrict__ gu, __nv_bfloat16* __restrict__ out) {
    size_t i = (size_t)blockIdx.x * 256 + threadIdx.x;
    if (i >= (size_t)Mq * FFq) return;
    size_t m = i / FFq; int kk = (int)(i % FFq);
    float g = gu[m * FFp + kk], u = gu[m * FFp + FFq + kk];
    float a = siluf(g) * u;
    __nv_bfloat16 hi = __float2bfloat16(a);
    __nv_bfloat16 lo = __float2bfloat16(a - __bfloat162float(hi));
    __nv_bfloat16* r = out + m * (size_t)(2 * FFq);
    r[kk] = hi; r[FFq + kk] = lo;           // [Ah|Al]
}

// ---------------- bf16 mma.sync GEMM, 128x128 tile, warp 64x32, occ 2 ---------
// A stored [Ah|Al] (width 2K), B stored [Bh|Bl] (width 2K); slab remap gives
// Ah*Bh + Al*Bh + Ah*Bl over nslab = 3*S1 slabs (S1 = K/64).
#define STG_A 16384
#define STG_B 16384
#define NSTAGE 3
#define GSMEM (1024 + NSTAGE*(STG_A + STG_B))

__global__ void __launch_bounds__(256, 2)
gemm_tc(const __nv_bfloat16* __restrict__ A, const __nv_bfloat16* __restrict__ B,
        const float* __restrict__ R, float* __restrict__ C,
        int N, int S1, int ld, int addR) {
    extern __shared__ char dsm[];
    uint32_t base = smem_u32(dsm);
    uint32_t uA = (base + 1023) & ~1023u;
    uint32_t uB = uA + NSTAGE * STG_A;

    const int tid = threadIdx.x;
    const int wid = tid >> 5, lane = tid & 31;
    const int bm = blockIdx.y * 128;
    const int bn = blockIdx.x * 128;
    const int wm = (wid & 1) * 64;
    const int wn = (wid >> 1) * 32;
    const int nslab = 3 * S1;

    auto fill = [&](int stg, int s) {
        int k0A = ((s < 2 * S1) ? s : s - 2 * S1) << 6;
        int k0B = ((s < S1) ? s : s - S1) << 6;
        const __nv_bfloat16* Ab = A + (size_t)bm * ld + k0A;
        const __nv_bfloat16* Bb = B + (size_t)bn * ld + k0B;
        uint32_t sA = uA + stg * STG_A, sB = uB + stg * STG_B;
        #pragma unroll
        for (int i = 0; i < 8; i++) {
            int id = tid + (i << 8);
            int row = (id & 1023) >> 3, c = id & 7;
            if (id < 1024) CP16(sA + SWZ(row * 128 + c * 16), Ab + (size_t)row * ld + c * 8);
            else           CP16(sB + SWZ(row * 128 + c * 16), Bb + (size_t)row * ld + c * 8);
        }
        CPCOMMIT();
    };

    float acc[4][4][4];
    #pragma unroll
    for (int mt = 0; mt < 4; mt++)
        #pragma unroll
        for (int nt = 0; nt < 4; nt++)
            #pragma unroll
            for (int j = 0; j < 4; j++) acc[mt][nt][j] = 0.f;

    fill(0, 0);
    if (nslab > 1) fill(1, 1); else CPCOMMIT();

    const int a_row = (lane & 15);
    const int a_sel = (lane >> 4);
    const int b_row = (lane & 7) + ((lane >> 4) << 3);
    const int b_sel = (lane >> 3) & 1;

    for (int s = 0; s < nslab; s++) {
        CPWAIT1();
        __syncthreads();
        // fill stage (s+2)%3 == (s-1)%3: consumed in iter s-1, safe after barrier
        if (s + 2 < nslab) fill((s + 2) % NSTAGE, s + 2);
        else CPCOMMIT();
        uint32_t sA = uA + (s % NSTAGE) * STG_A;
        uint32_t sB = uB + (s % NSTAGE) * STG_B;
        #pragma unroll
        for (int ks = 0; ks < 4; ks++) {
            uint32_t a[4][4], b[4][2];
            #pragma unroll
            for (int mt = 0; mt < 4; mt++) {
                uint32_t addr = sA + SWZ((wm + mt * 16 + a_row) * 128 + (ks * 2 + a_sel) * 16);
                LDMX4(a[mt][0], a[mt][1], a[mt][2], a[mt][3], addr);
            }
            #pragma unroll
            for (int bt = 0; bt < 2; bt++) {
                uint32_t addr = sB + SWZ((wn + bt * 16 + b_row) * 128 + (ks * 2 + b_sel) * 16);
                LDMX4(b[bt*2][0], b[bt*2][1], b[bt*2+1][0], b[bt*2+1][1], addr);
            }
            #pragma unroll
            for (int mt = 0; mt < 4; mt++)
                #pragma unroll
                for (int nt = 0; nt < 4; nt++)
                    MMA16816(acc[mt][nt], a[mt], b[nt]);
        }
        // no trailing barrier: next iteration's barrier is the hazard fence
    }

    #pragma unroll
    for (int mt = 0; mt < 4; mt++) {
        #pragma unroll
        for (int h = 0; h < 2; h++) {
            int row = bm + wm + mt * 16 + (lane >> 2) + h * 8;
            float* crow = C + (size_t)row * N + bn + wn + 2 * (lane & 3);
            const float* rrow = addR ? (R + (size_t)row * N + bn + wn + 2 * (lane & 3)) : nullptr;
            #pragma unroll
            for (int nt = 0; nt < 4; nt++) {
                float2 ov = make_float2(acc[mt][nt][h*2], acc[mt][nt][h*2+1]);
                if (addR) {
                    float2 rv = *(const float2*)(rrow + nt * 8);
                    ov.x += rv.x; ov.y += rv.y;
                }
                *(float2*)(crow + nt * 8) = ov;
            }
        }
    }
}

// ---------------- fused RMSNorm -> bf16 [Ah|Al] --------------------------------
__global__ void rmsnorm_split_kernel(const float* __restrict__ x, const float* __restrict__ w,
                                     __nv_bfloat16* __restrict__ outb) {
    int row = blockIdx.x;
    float4 v = ((const float4*)(x + (size_t)row * Dq))[threadIdx.x];
    float ss = v.x*v.x + v.y*v.y + v.z*v.z + v.w*v.w;
    #pragma unroll
    for (int o = 16; o; o >>= 1) ss += __shfl_xor_sync(0xffffffffu, ss, o);
    __shared__ float red[8];
    int wd = threadIdx.x >> 5, ln = threadIdx.x & 31;
    if (ln == 0) red[wd] = ss;
    __syncthreads();
    float tot = red[0]+red[1]+red[2]+red[3]+red[4]+red[5]+red[6]+red[7];
    float r = rsqrtf(tot * (1.0f / Dq) + 1e-6f);
    float4 wv = ((const float4*)w)[threadIdx.x];
    float4 ov = make_float4(v.x*r*wv.x, v.y*r*wv.y, v.z*r*wv.z, v.w*r*wv.w);
    ull hi, lo; split4(ov, hi, lo);
    __nv_bfloat16* rb = outb + (size_t)row * 2048 + threadIdx.x * 4;
    *(ull*)rb = hi;
    *(ull*)(rb + 1024) = lo;
}

// ---------------- fused conv+silu+l2norm for q AND k (one launch) -------------
__global__ void conv_l2_kernel(const float* __restrict__ in, int stride,
                               const float* __restrict__ wq, const float* __restrict__ wk,
                               float* __restrict__ outq, float* __restrict__ outk) {
    int vec = blockIdx.x * 8 + (threadIdx.x >> 5);   // bt*16 + h
    int lane = threadIdx.x & 31;
    int bt = vec >> 4, h = vec & 15;
    int t = bt & (Tq - 1);
    int c = h * 64 + lane * 2;
    int isK = blockIdx.y;
    const float* w = isK ? wk : wq;
    float* out = isK ? outk : outq;
    float scale = isK ? 1.0f : 0.125f;
    const float* p = in + (size_t)bt * stride + isK * 1024 + c;
    float2 x0 = *(const float2*)p;
    float2 x1 = (t >= 1) ? *(const float2*)(p - stride)     : make_float2(0.f, 0.f);
    float2 x2 = (t >= 2) ? *(const float2*)(p - 2 * stride) : make_float2(0.f, 0.f);
    float2 x3 = (t >= 3) ? *(const float2*)(p - 3 * stride) : make_float2(0.f, 0.f);
    float4 w0 = ((const float4*)w)[c];
    float4 w1 = ((const float4*)w)[c + 1];
    float a0 = w0.w*x0.x + w0.z*x1.x + w0.y*x2.x + w0.x*x3.x;
    float a1 = w1.w*x0.y + w1.z*x1.y + w1.y*x2.y + w1.x*x3.y;
    a0 = siluf(a0); a1 = siluf(a1);
    float ss = a0*a0 + a1*a1;
    #pragma unroll
    for (int o = 16; o; o >>= 1) ss += __shfl_xor_sync(0xffffffffu, ss, o);
    float r = rsqrtf(ss + 1e-6f) * scale;
    *(float2*)(out + (size_t)bt * Dq + c) = make_float2(a0 * r, a1 * r);
}

// ---------------- conv+silu for v (elementwise) -------------------------------
__global__ void conv_silu_kernel(const float* __restrict__ in, int stride,
                                 const float* __restrict__ w,
                                 float* __restrict__ out, int C) {
    size_t idx = (size_t)blockIdx.x * 256 + threadIdx.x;
    if (idx >= (size_t)Mq * C) return;
    int c = (int)(idx % C);
    size_t bt = idx / C;
    int t = (int)(bt % Tq);
    const float* p = in + bt * (size_t)stride + c;
    float4 wv = ((const float4*)w)[c];
    float acc = wv.w * p[0];
    if (t >= 1) acc += wv.z * p[-(ptrdiff_t)stride];
    if (t >= 2) acc += wv.y * p[-2 * (ptrdiff_t)stride];
    if (t >= 3) acc += wv.x * p[-3 * (ptrdiff_t)stride];
    out[idx] = siluf(acc);
}

// ba reads bf16 [Ah|Al] activations (hi+lo ~ fp32 to 2^-17)
__global__ void ba_kernel(const __nv_bfloat16* __restrict__ hA, const float* __restrict__ b_w,
                          const float* __restrict__ a_w, const float* __restrict__ A_log,
                          const float* __restrict__ dt_bias,
                          float* __restrict__ beta, float* __restrict__ dec) {
    int row = blockIdx.x * 4 + (threadIdx.x >> 5);
    int lane = threadIdx.x & 31;
    int c = lane & 15;
    const float* W = (lane < 16) ? b_w : a_w;
    const __nv_bfloat16* hr = hA + (size_t)row * 2048;
    float a0 = 0.f, a1 = 0.f;
    for (int kk = 0; kk < Dq; kk += 2) {
        float h0 = __bfloat162float(hr[kk])   + __bfloat162float(hr[1024 + kk]);
        float h1 = __bfloat162float(hr[kk+1]) + __bfloat162float(hr[1024 + kk + 1]);
        a0 += h0 * W[kk * Hq + c];
        a1 += h1 * W[(kk + 1) * Hq + c];
    }
    float acc = a0 + a1;
    if (lane < 16) {
        beta[(size_t)row * Hq + c] = 1.0f / (1.0f + __expf(-acc));
    } else {
        float xv = acc + dt_bias[c];
        float sp = fmaxf(xv, 0.f) + log1pf(__expf(-fabsf(xv)));
        dec[(size_t)row * Hq + c] = __expf(-__expf(A_log[c]) * sp);
    }
}

// ---------------- fused gated RMSNorm -> bf16 [Ah|Al] --------------------------
__global__ void gated_split_kernel(const float* __restrict__ o, const float* __restrict__ w,
                                   const float* __restrict__ gate, int gstride,
                                   __nv_bfloat16* __restrict__ outb) {
    int vec = blockIdx.x * 8 + (threadIdx.x >> 5);
    int lane = threadIdx.x & 31;
    int m = vec >> 4, hh = vec & 15;
    const float4* op = (const float4*)(o + (size_t)vec * DVq);
    const float4* gp = (const float4*)(gate + (size_t)m * gstride + hh * DVq);
    float4 v = op[lane];
    float ss = v.x*v.x + v.y*v.y + v.z*v.z + v.w*v.w;
    #pragma unroll
    for (int off = 16; off; off >>= 1) ss += __shfl_xor_sync(0xffffffffu, ss, off);
    float r = rsqrtf(ss * (1.0f / DVq) + 1e-6f);
    float4 wv = ((const float4*)w)[lane];
    float4 g = gp[lane];
    float4 ov = make_float4(v.x*r*wv.x*siluf(g.x), v.y*r*wv.y*siluf(g.y),
                            v.z*r*wv.z*siluf(g.z), v.w*r*wv.w*siluf(g.w));
    ull hi, lo; split4(ov, hi, lo);
    __nv_bfloat16* rb = outb + (size_t)m * 4096 + hh * DVq + lane * 4;
    *(ull*)rb = hi;
    *(ull*)(rb + 2048) = lo;
}

// ---------------- gated delta-rule scan (unchanged from R10) -------------------
#define RSTRIDE 196
__global__ void __launch_bounds__(128)
scan_kernel(const float* __restrict__ q, const float* __restrict__ k,
            const float* __restrict__ v, const float* __restrict__ dec,
            const float* __restrict__ bt, float* __restrict__ o) {
    __shared__ alignas(16) float ring[16 * RSTRIDE];
    int quarter = blockIdx.x & 3;
    int bh = blockIdx.x >> 2;
    int b = bh >> 4, h = bh & 15;
    int tid = threadIdx.x;
    int colL = tid >> 2, sub = tid & 3;
    int col = quarter * 32 + colL;

    size_t rowBase = (size_t)b * Tq;
    const float* kb = k + rowBase * Dq + h * DKq;
    const float* qb = q + rowBase * Dq + h * DKq;
    const float* vb = v + rowBase * VDq + h * DVq + quarter * 32;
    const float* db = dec + rowBase * Hq + h;
    const float* bb = bt + rowBase * Hq + h;
    float* ob = o + rowBase * VDq + h * DVq + col;

    uint32_t ringU = smem_u32(ring);

    auto fill = [&](int hf, int blk) {
        #pragma unroll
        for (int rep = 0; rep < 3; rep++) {
            int idx = tid + rep * 128;
            if (idx < 336) {
                int sid = idx / 42, slot = idx % 42;
                int t = blk * 8 + sid;
                uint32_t sb = ringU + ((hf * 8 + sid) * RSTRIDE) * 4;
                if (slot < 16) {
                    int ch = slot >> 2, i = slot & 3;
                    CP16(sb + (ch * 20 + i * 4) * 4,      kb + (size_t)t * Dq + ch * 16 + i * 4);
                } else if (slot < 32) {
                    int s2 = slot - 16, ch = s2 >> 2, i = s2 & 3;
                    CP16(sb + (80 + ch * 20 + i * 4) * 4, qb + (size_t)t * Dq + ch * 16 + i * 4);
                } else if (slot < 40) {
                    CP16(sb + (160 + (slot - 32) * 4) * 4, vb + (size_t)t * VDq + (slot - 32) * 4);
                } else if (slot == 40) {
                    CP4(sb + 192 * 4, db + (size_t)t * Hq);
                } else {
                    CP4(sb + 193 * 4, bb + (size_t)t * Hq);
                }
            }
        }
        CPCOMMIT();
    };

    ull S[8];
    #pragma unroll
    for (int p = 0; p < 8; p++) S[p] = 0ull;

    fill(0, 0);
    fill(1, 1);

    for (int blk = 0; blk < 256; blk++) {
        CPWAIT1();
        __syncthreads();
        int hf = blk & 1;
        #pragma unroll 1
        for (int j = 0; j < 8; j++) {
            const float* st = &ring[(hf * 8 + j) * RSTRIDE];
            const ull* kp = (const ull*)(st + sub * 20);
            const ull* qp = (const ull*)(st + 80 + sub * 20);
            float vt = st[160 + colL];
            float d = st[192], bet = st[193];
            ull kr[8], qr[8];
            #pragma unroll
            for (int p = 0; p < 8; p++) { kr[p] = kp[p]; qr[p] = qp[p]; }
            ull ksa = 0ull, ksb = 0ull, qsa = 0ull, qsb = 0ull, qka = 0ull, qkb = 0ull;
            #pragma unroll
            for (int p = 0; p < 8; p += 2) {
                ksa = ffma2(kr[p],   S[p],    ksa);
                ksb = ffma2(kr[p+1], S[p+1],  ksb);
                qsa = ffma2(qr[p],   S[p],    qsa);
                qsb = ffma2(qr[p+1], S[p+1],  qsb);
                qka = ffma2(qr[p],   kr[p],   qka);
                qkb = ffma2(qr[p+1], kr[p+1], qkb);
            }
            float2 f0 = unpk(ksa), f1 = unpk(ksb);
            float2 f2 = unpk(qsa), f3 = unpk(qsb);
            float2 f4 = unpk(qka), f5 = unpk(qkb);
            float ks = (f0.x + f0.y) + (f1.x + f1.y);
            float qs = (f2.x + f2.y) + (f3.x + f3.y);
            float qk = (f4.x + f4.y) + (f5.x + f5.y);
            ks += __shfl_xor_sync(0xffffffffu, ks, 1);
            qs += __shfl_xor_sync(0xffffffffu, qs, 1);
            qk += __shfl_xor_sync(0xffffffffu, qk, 1);
            ks += __shfl_xor_sync(0xffffffffu, ks, 2);
            qs += __shfl_xor_sync(0xffffffffu, qs, 2);
            qk += __shfl_xor_sync(0xffffffffu, qk, 2);
            float vp = d * ks;
            float u = bet * (vt - vp);
            float ot = d * qs + qk * u;
            ull up = dup2(u), dpk = dup2(d);
            #pragma unroll
            for (int p = 0; p < 8; p++)
                S[p] = ffma2(kr[p], up, mul2(S[p], dpk));
            if (sub == 0) ob[(size_t)(blk * 8 + j) * VDq] = ot;
        }
        __syncthreads();
        if (blk + 2 < 256) fill(hf, blk + 2);
        else CPCOMMIT();
    }
}

// ---------------- host orchestration -----------------------------------------
static inline void launch_gemm(const __nv_bfloat16* A, const __nv_bfloat16* B,
                               const float* R, float* C, int N, int S1, int ld, int addR) {
    dim3 grid(N / 128, Mq / 128);
    gemm_tc<<<grid, 256, GSMEM>>>(A, B, R, C, N, S1, ld, addR);
}

extern "C" void kernel_launch(void* const* d_in, const int* in_sizes, int n_in,
                              void* d_out, int out_size) {
    const float* hidden   = (const float*)d_in[0];
    const float* norm_w   = (const float*)d_in[1];
    const float* q_w      = (const float*)d_in[2];
    const float* k_w      = (const float*)d_in[3];
    const float* v_w      = (const float*)d_in[4];
    const float* b_w      = (const float*)d_in[5];
    const float* a_w      = (const float*)d_in[6];
    const float* A_log    = (const float*)d_in[7];
    const float* dt_bias  = (const float*)d_in[8];
    const float* conv_q_w = (const float*)d_in[9];
    const float* conv_k_w = (const float*)d_in[10];
    const float* conv_v_w = (const float*)d_in[11];
    const float* g_wm     = (const float*)d_in[12];
    const float* o_norm_w = (const float*)d_in[13];
    const float* o_w      = (const float*)d_in[14];
    const float* post_w   = (const float*)d_in[15];
    const float* gate_w   = (const float*)d_in[16];
    const float* up_w     = (const float*)d_in[17];
    const float* down_w   = (const float*)d_in[18];
    float* out = (float*)d_out;

    float *p_qkvg, *p_q, *p_k, *p_v, *p_bt, *p_gd, *p_o, *p_x, *p_gu;
    __nv_bfloat16 *p_A, *p_Bqkvg, *p_Bo, *p_Bmlp, *p_Bdwn;
    cudaGetSymbolAddress((void**)&p_qkvg, g_qkvg);
    cudaGetSymbolAddress((void**)&p_q, g_q);
    cudaGetSymbolAddress((void**)&p_k, g_k);
    cudaGetSymbolAddress((void**)&p_v, g_v);
    cudaGetSymbolAddress((void**)&p_bt, g_bt);
    cudaGetSymbolAddress((void**)&p_gd, g_gd);
    cudaGetSymbolAddress((void**)&p_o, g_o);
    cudaGetSymbolAddress((void**)&p_x, g_x);
    cudaGetSymbolAddress((void**)&p_gu, g_gu);
    cudaGetSymbolAddress((void**)&p_A, g_Aexp);
    cudaGetSymbolAddress((void**)&p_Bqkvg, g_Bqkvg);
    cudaGetSymbolAddress((void**)&p_Bo, g_Bo);
    cudaGetSymbolAddress((void**)&p_Bmlp, g_Bmlp);
    cudaGetSymbolAddress((void**)&p_Bdwn, g_Bdwn);

    cudaFuncSetAttribute(gemm_tc, cudaFuncAttributeMaxDynamicSharedMemorySize, GSMEM);

    // weight conversion: one combined launch, [Bh|Bl] layout
    SJobs jobs;
    auto setjob = [&](int j, const float* s, __nv_bfloat16* d, int K, int N) {
        jobs.src[j] = s; jobs.dst[j] = d; jobs.K[j] = K; jobs.N[j] = N;
        jobs.nx[j] = N / 32; jobs.blocks[j] = (N / 32) * (K / 32);
    };
    setjob(0, q_w,    p_Bqkvg,                        1024, 1024);
    setjob(1, k_w,    p_Bqkvg + (size_t)1024 * 2048,  1024, 1024);
    setjob(2, v_w,    p_Bqkvg + (size_t)2048 * 2048,  1024, 2048);
    setjob(3, g_wm,   p_Bqkvg + (size_t)4096 * 2048,  1024, 2048);
    setjob(4, o_w,    p_Bo,                           2048, 1024);
    setjob(5, gate_w, p_Bmlp,                         1024, 2752);
    setjob(6, up_w,   p_Bmlp + (size_t)2752 * 2048,   1024, 2752);
    setjob(7, down_w, p_Bdwn,                         2752, 1024);
    int total_blocks = 0;
    for (int j = 0; j < 8; j++) total_blocks += jobs.blocks[j];
    splitT_all<<<total_blocks, dim3(32, 8)>>>(jobs);
    cudaMemsetAsync(p_Bmlp + (size_t)5504 * 2048, 0, (size_t)128 * 2048 * sizeof(__nv_bfloat16));

    // 1) pre-norm -> bf16 [Ah|Al]; ba reads the bf16 pair
    rmsnorm_split_kernel<<<Mq, 256>>>(hidden, norm_w, p_A);
    ba_kernel<<<Mq / 4, 128>>>(p_A, b_w, a_w, A_log, dt_bias, p_bt, p_gd);

    // 2) fused q|k|v|gate projection (N=6144, K=1024 -> S1=16, ld=2048)
    launch_gemm(p_A, p_Bqkvg, nullptr, p_qkvg, 6144, 16, 2048, 0);

    // 3) conv+silu(+l2norm) for q and k (one launch), conv+silu for v
    conv_l2_kernel<<<dim3((Mq * Hq) / 8, 2), 256>>>(p_qkvg, 6144, conv_q_w, conv_k_w, p_q, p_k);
    conv_silu_kernel<<<(int)(((size_t)Mq * 2048 + 255) / 256), 256>>>(p_qkvg + 2048, 6144, conv_v_w, p_v, 2048);

    // 4) scan
    scan_kernel<<<Bq * Hq * 4, 128>>>(p_q, p_k, p_v, p_gd, p_bt, p_o);

    // 5) gated per-head RMSNorm -> bf16 [Ah|Al] (width 4096)
    gated_split_kernel<<<(Mq * Hq) / 8, 256>>>(p_o, o_norm_w, p_qkvg + 4096, 6144, p_A);

    // 6) output projection + residual (K=2048 -> S1=32, ld=4096)
    launch_gemm(p_A, p_Bo, hidden, p_x, 1024, 32, 4096, 1);

    // 7) post norm -> bf16 [Ah|Al]
    rmsnorm_split_kernel<<<Mq, 256>>>(p_x, post_w, p_A);

    // 8) MLP (K=1024 -> S1=16; down K=2752 -> S1=43, ld=5504)
    launch_gemm(p_A, p_Bmlp, nullptr, p_gu, FFp, 16, 2048, 0);
    act_split<<<(int)(((size_t)Mq * FFq + 255) / 256), 256>>>(p_gu, p_A);
    launch_gemm(p_A, p_Bdwn, p_x, out, 1024, 43, 5504, 1);
}

// round 12
// speedup vs baseline: 1.0337x; 1.0337x over previous
#include <cuda_runtime.h>
#include <cuda_bf16.h>
#include <cstdint>

#define Bq 2
#define Tq 2048
#define Dq 1024
#define VDq 2048
#define FFq 2752
#define FFp 5632
#define Hq 16
#define DKq 64
#define DVq 128
#define Mq (Bq*Tq)      // 4096

// ---------------- device scratch --------------------------------------------
__device__ float g_qkvg[Mq*(size_t)6144];
__device__ float g_q   [Mq*(size_t)Dq];
__device__ float g_k   [Mq*(size_t)Dq];
__device__ float g_v   [Mq*(size_t)VDq];
__device__ float g_bt  [Mq*(size_t)Hq];
__device__ float g_gd  [Mq*(size_t)Hq];     // exp(g) decay
__device__ float g_o   [Mq*(size_t)VDq];
__device__ float g_x   [Mq*(size_t)Dq];
__device__ float g_gu  [Mq*(size_t)FFp];
__device__ __nv_bfloat16 g_Aexp [Mq*(size_t)5504];      // [Ah|Al]
__device__ __nv_bfloat16 g_Bqkvg[(size_t)6144*2048];    // [Bh|Bl] per row
__device__ __nv_bfloat16 g_Bo   [(size_t)1024*4096];
__device__ __nv_bfloat16 g_Bmlp [(size_t)FFp*2048];
__device__ __nv_bfloat16 g_Bdwn [(size_t)1024*5504];

// ---------------- PTX helpers ------------------------------------------------
__device__ __forceinline__ uint32_t smem_u32(const void* p) {
    uint32_t a;
    asm("{ .reg .u64 t; cvta.to.shared.u64 t, %1; cvt.u32.u64 %0, t; }" : "=r"(a) : "l"(p));
    return a;
}
typedef unsigned long long ull;
__device__ __forceinline__ ull ffma2(ull a, ull b, ull c) {
    ull d; asm("fma.rn.f32x2 %0,%1,%2,%3;" : "=l"(d) : "l"(a), "l"(b), "l"(c)); return d;
}
__device__ __forceinline__ ull mul2(ull a, ull b) {
    ull d; asm("mul.rn.f32x2 %0,%1,%2;" : "=l"(d) : "l"(a), "l"(b)); return d;
}
__device__ __forceinline__ ull dup2(float x) {
    ull r; asm("mov.b64 %0, {%1,%1};" : "=l"(r) : "f"(x)); return r;
}
__device__ __forceinline__ float2 unpk(ull a) {
    float2 f; asm("mov.b64 {%0,%1}, %2;" : "=f"(f.x), "=f"(f.y) : "l"(a)); return f;
}
__device__ __forceinline__ float siluf(float x) { return x / (1.0f + __expf(-x)); }

__device__ __forceinline__ void split4(float4 v, ull& hi, ull& lo) {
    __nv_bfloat16 h0 = __float2bfloat16(v.x), h1 = __float2bfloat16(v.y),
                  h2 = __float2bfloat16(v.z), h3 = __float2bfloat16(v.w);
    __nv_bfloat16 l0 = __float2bfloat16(v.x - __bfloat162float(h0));
    __nv_bfloat16 l1 = __float2bfloat16(v.y - __bfloat162float(h1));
    __nv_bfloat16 l2 = __float2bfloat16(v.z - __bfloat162float(h2));
    __nv_bfloat16 l3 = __float2bfloat16(v.w - __bfloat162float(h3));
    ushort4 hu = make_ushort4(__bfloat16_as_ushort(h0), __bfloat16_as_ushort(h1),
                              __bfloat16_as_ushort(h2), __bfloat16_as_ushort(h3));
    ushort4 lu = make_ushort4(__bfloat16_as_ushort(l0), __bfloat16_as_ushort(l1),
                              __bfloat16_as_ushort(l2), __bfloat16_as_ushort(l3));
    hi = *(ull*)&hu; lo = *(ull*)&lu;
}

#define SWZ(o) ((o) ^ (((o) >> 3) & 0x70))
#define CP16(d, s) asm volatile("cp.async.cg.shared.global [%0], [%1], 16;" :: "r"(d), "l"(s) : "memory")
#define CP4(d, s)  asm volatile("cp.async.ca.shared.global [%0], [%1], 4;"  :: "r"(d), "l"(s) : "memory")
#define CPCOMMIT() asm volatile("cp.async.commit_group;" ::: "memory")
#define CPWAIT1()  asm volatile("cp.async.wait_group 1;" ::: "memory")
#define CPWAIT2()  asm volatile("cp.async.wait_group 2;" ::: "memory")

#define LDMX4(r0,r1,r2,r3,addr) \
    asm volatile("ldmatrix.sync.aligned.m8n8.x4.shared.b16 {%0,%1,%2,%3}, [%4];" \
                 : "=r"(r0), "=r"(r1), "=r"(r2), "=r"(r3) : "r"(addr))

#define MMA16816(c, a, b) \
    asm volatile("mma.sync.aligned.m16n8k16.row.col.f32.bf16.bf16.f32 " \
                 "{%0,%1,%2,%3}, {%4,%5,%6,%7}, {%8,%9}, {%0,%1,%2,%3};" \
                 : "+f"((c)[0]), "+f"((c)[1]), "+f"((c)[2]), "+f"((c)[3]) \
                 : "r"((a)[0]), "r"((a)[1]), "r"((a)[2]), "r"((a)[3]), \
                   "r"((b)[0]), "r"((b)[1]))

// ---------------- combined weight split/transpose (one launch) ---------------
struct SJobs {
    const float* src[8];
    __nv_bfloat16* dst[8];
    int K[8], N[8], nx[8], blocks[8];
};

__global__ void splitT_all(SJobs jb) {
    __shared__ float tile[32][33];
    int bx = blockIdx.x, j = 0, base = 0;
    for (j = 0; j < 8; j++) {
        if (bx < base + jb.blocks[j]) break;
        base += jb.blocks[j];
    }
    int local = bx - base;
    int K = jb.K[j], N = jb.N[j];
    const float* W = jb.src[j];
    __nv_bfloat16* out = jb.dst[j];
    int n0 = (local % jb.nx[j]) * 32;
    int k0 = (local / jb.nx[j]) * 32;

    for (int r = threadIdx.y; r < 32; r += 8)
        tile[r][threadIdx.x] = W[(size_t)(k0 + r) * N + n0 + threadIdx.x];
    __syncthreads();
    for (int r = threadIdx.y; r < 32; r += 8) {
        int n = n0 + r, kk = k0 + threadIdx.x;
        float x = tile[threadIdx.x][r];
        __nv_bfloat16 hi = __float2bfloat16(x);
        __nv_bfloat16 lo = __float2bfloat16(x - __bfloat162float(hi));
        __nv_bfloat16* orow = out + (size_t)n * (2 * K);
        orow[kk] = hi; orow[K + kk] = lo;   // [Bh|Bl]
    }
}

__global__ void act_split(const float* __restrict__ gu, __nv_bfloat16* __restrict__ out) {
    size_t i = (size_t)blockIdx.x * 256 + threadIdx.x;
    if (i >= (size_t)Mq * FFq) return;
    size_t m = i / FFq; int kk = (int)(i % FFq);
    float g = gu[m * FFp + kk], u = gu[m * FFp + FFq + kk];
    float a = siluf(g) * u;
    __nv_bfloat16 hi = __float2bfloat16(a);
    __nv_bfloat16 lo = __float2bfloat16(a - __bfloat162float(hi));
    __nv_bfloat16* r = out + m * (size_t)(2 * FFq);
    r[kk] = hi; r[FFq + kk] = lo;           // [Ah|Al]
}

// ---------------- bf16 mma.sync GEMM, 128x256 CTA tile, warp 64x64, occ 1 -----
// A stored [Ah|Al] (width 2K), B stored [Bh|Bl] (width 2K); slab remap gives
// Ah*Bh + Al*Bh + Ah*Bl over nslab = 3*S1 slabs (S1 = K/64).
// 4-stage cp.async pipeline; fill issued BEFORE compute; single barrier/slab.
#define STG_A 16384
#define STG_B 32768
#define NSTAGE 4
#define GSMEM (1024 + NSTAGE*(STG_A + STG_B))

__global__ void __launch_bounds__(256, 1)
gemm_tc(const __nv_bfloat16* __restrict__ A, const __nv_bfloat16* __restrict__ B,
        const float* __restrict__ R, float* __restrict__ C,
        int N, int S1, int ld, int addR) {
    extern __shared__ char dsm[];
    uint32_t base = smem_u32(dsm);
    uint32_t uA = (base + 1023) & ~1023u;
    uint32_t uB = uA + NSTAGE * STG_A;

    const int tid = threadIdx.x;
    const int wid = tid >> 5, lane = tid & 31;
    const int bm = blockIdx.y * 128;
    const int bn = blockIdx.x * 256;
    const int wm = (wid & 1) * 64;
    const int wn = (wid >> 1) * 64;
    const int nslab = 3 * S1;

    auto fill = [&](int stg, int s) {
        int k0A = ((s < 2 * S1) ? s : s - 2 * S1) << 6;
        int k0B = ((s < S1) ? s : s - S1) << 6;
        const __nv_bfloat16* Ab = A + (size_t)bm * ld + k0A;
        const __nv_bfloat16* Bb = B + (size_t)bn * ld + k0B;
        uint32_t sA = uA + stg * STG_A, sB = uB + stg * STG_B;
        #pragma unroll
        for (int i = 0; i < 12; i++) {
            int id = tid + (i << 8);
            if (id < 1024) {
                int row = id >> 3, c = id & 7;
                CP16(sA + SWZ(row * 128 + c * 16), Ab + (size_t)row * ld + c * 8);
            } else {
                int bid = id - 1024;
                int row = bid >> 3, c = bid & 7;
                CP16(sB + SWZ(row * 128 + c * 16), Bb + (size_t)row * ld + c * 8);
            }
        }
        CPCOMMIT();
    };

    float acc[4][8][4];
    #pragma unroll
    for (int mt = 0; mt < 4; mt++)
        #pragma unroll
        for (int nt = 0; nt < 8; nt++)
            #pragma unroll
            for (int j = 0; j < 4; j++) acc[mt][nt][j] = 0.f;

    fill(0, 0);
    if (nslab > 1) fill(1, 1); else CPCOMMIT();
    if (nslab > 2) fill(2, 2); else CPCOMMIT();

    const int a_row = (lane & 15);
    const int a_sel = (lane >> 4);
    const int b_row = (lane & 7) + ((lane >> 4) << 3);
    const int b_sel = (lane >> 3) & 1;

    for (int s = 0; s < nslab; s++) {
        CPWAIT2();
        __syncthreads();
        // fill stage (s+3)%4 == (s-1)%4: consumed in iter s-1, safe after barrier
        if (s + 3 < nslab) fill((s + 3) % NSTAGE, s + 3);
        else CPCOMMIT();
        uint32_t sA = uA + (s % NSTAGE) * STG_A;
        uint32_t sB = uB + (s % NSTAGE) * STG_B;
        #pragma unroll
        for (int ks = 0; ks < 4; ks++) {
            uint32_t a[4][4], b[8][2];
            #pragma unroll
            for (int mt = 0; mt < 4; mt++) {
                uint32_t addr = sA + SWZ((wm + mt * 16 + a_row) * 128 + (ks * 2 + a_sel) * 16);
                LDMX4(a[mt][0], a[mt][1], a[mt][2], a[mt][3], addr);
            }
            #pragma unroll
            for (int bt = 0; bt < 4; bt++) {
                uint32_t addr = sB + SWZ((wn + bt * 16 + b_row) * 128 + (ks * 2 + b_sel) * 16);
                LDMX4(b[bt*2][0], b[bt*2][1], b[bt*2+1][0], b[bt*2+1][1], addr);
            }
            #pragma unroll
            for (int mt = 0; mt < 4; mt++)
                #pragma unroll
                for (int nt = 0; nt < 8; nt++)
                    MMA16816(acc[mt][nt], a[mt], b[nt]);
        }
        // no trailing barrier: next iteration's barrier is the hazard fence
    }

    #pragma unroll
    for (int mt = 0; mt < 4; mt++) {
        #pragma unroll
        for (int h = 0; h < 2; h++) {
            int row = bm + wm + mt * 16 + (lane >> 2) + h * 8;
            float* crow = C + (size_t)row * N + bn + wn + 2 * (lane & 3);
            const float* rrow = addR ? (R + (size_t)row * N + bn + wn + 2 * (lane & 3)) : nullptr;
            #pragma unroll
            for (int nt = 0; nt < 8; nt++) {
                float2 ov = make_float2(acc[mt][nt][h*2], acc[mt][nt][h*2+1]);
                if (addR) {
                    float2 rv = *(const float2*)(rrow + nt * 8);
                    ov.x += rv.x; ov.y += rv.y;
                }
                *(float2*)(crow + nt * 8) = ov;
            }
        }
    }
}

// ---------------- fused RMSNorm -> bf16 [Ah|Al] --------------------------------
__global__ void rmsnorm_split_kernel(const float* __restrict__ x, const float* __restrict__ w,
                                     __nv_bfloat16* __restrict__ outb) {
    int row = blockIdx.x;
    float4 v = ((const float4*)(x + (size_t)row * Dq))[threadIdx.x];
    float ss = v.x*v.x + v.y*v.y + v.z*v.z + v.w*v.w;
    #pragma unroll
    for (int o = 16; o; o >>= 1) ss += __shfl_xor_sync(0xffffffffu, ss, o);
    __shared__ float red[8];
    int wd = threadIdx.x >> 5, ln = threadIdx.x & 31;
    if (ln == 0) red[wd] = ss;
    __syncthreads();
    float tot = red[0]+red[1]+red[2]+red[3]+red[4]+red[5]+red[6]+red[7];
    float r = rsqrtf(tot * (1.0f / Dq) + 1e-6f);
    float4 wv = ((const float4*)w)[threadIdx.x];
    float4 ov = make_float4(v.x*r*wv.x, v.y*r*wv.y, v.z*r*wv.z, v.w*r*wv.w);
    ull hi, lo; split4(ov, hi, lo);
    __nv_bfloat16* rb = outb + (size_t)row * 2048 + threadIdx.x * 4;
    *(ull*)rb = hi;
    *(ull*)(rb + 1024) = lo;
}

// ---------------- fused conv+silu+l2norm for q AND k (one launch) -------------
__global__ void conv_l2_kernel(const float* __restrict__ in, int stride,
                               const float* __restrict__ wq, const float* __restrict__ wk,
                               float* __restrict__ outq, float* __restrict__ outk) {
    int vec = blockIdx.x * 8 + (threadIdx.x >> 5);   // bt*16 + h
    int lane = threadIdx.x & 31;
    int bt = vec >> 4, h = vec & 15;
    int t = bt & (Tq - 1);
    int c = h * 64 + lane * 2;
    int isK = blockIdx.y;
    const float* w = isK ? wk : wq;
    float* out = isK ? outk : outq;
    float scale = isK ? 1.0f : 0.125f;
    const float* p = in + (size_t)bt * stride + isK * 1024 + c;
    float2 x0 = *(const float2*)p;
    float2 x1 = (t >= 1) ? *(const float2*)(p - stride)     : make_float2(0.f, 0.f);
    float2 x2 = (t >= 2) ? *(const float2*)(p - 2 * stride) : make_float2(0.f, 0.f);
    float2 x3 = (t >= 3) ? *(const float2*)(p - 3 * stride) : make_float2(0.f, 0.f);
    float4 w0 = ((const float4*)w)[c];
    float4 w1 = ((const float4*)w)[c + 1];
    float a0 = w0.w*x0.x + w0.z*x1.x + w0.y*x2.x + w0.x*x3.x;
    float a1 = w1.w*x0.y + w1.z*x1.y + w1.y*x2.y + w1.x*x3.y;
    a0 = siluf(a0); a1 = siluf(a1);
    float ss = a0*a0 + a1*a1;
    #pragma unroll
    for (int o = 16; o; o >>= 1) ss += __shfl_xor_sync(0xffffffffu, ss, o);
    float r = rsqrtf(ss + 1e-6f) * scale;
    *(float2*)(out + (size_t)bt * Dq + c) = make_float2(a0 * r, a1 * r);
}

// ---------------- conv+silu for v (elementwise) -------------------------------
__global__ void conv_silu_kernel(const float* __restrict__ in, int stride,
                                 const float* __restrict__ w,
                                 float* __restrict__ out, int C) {
    size_t idx = (size_t)blockIdx.x * 256 + threadIdx.x;
    if (idx >= (size_t)Mq * C) return;
    int c = (int)(idx % C);
    size_t bt = idx / C;
    int t = (int)(bt % Tq);
    const float* p = in + bt * (size_t)stride + c;
    float4 wv = ((const float4*)w)[c];
    float acc = wv.w * p[0];
    if (t >= 1) acc += wv.z * p[-(ptrdiff_t)stride];
    if (t >= 2) acc += wv.y * p[-2 * (ptrdiff_t)stride];
    if (t >= 3) acc += wv.x * p[-3 * (ptrdiff_t)stride];
    out[idx] = siluf(acc);
}

// ba reads bf16 [Ah|Al] activations (hi+lo ~ fp32 to 2^-17)
__global__ void ba_kernel(const __nv_bfloat16* __restrict__ hA, const float* __restrict__ b_w,
                          const float* __restrict__ a_w, const float* __restrict__ A_log,
                          const float* __restrict__ dt_bias,
                          float* __restrict__ beta, float* __restrict__ dec) {
    int row = blockIdx.x * 4 + (threadIdx.x >> 5);
    int lane = threadIdx.x & 31;
    int c = lane & 15;
    const float* W = (lane < 16) ? b_w : a_w;
    const __nv_bfloat16* hr = hA + (size_t)row * 2048;
    float a0 = 0.f, a1 = 0.f;
    for (int kk = 0; kk < Dq; kk += 2) {
        float h0 = __bfloat162float(hr[kk])   + __bfloat162float(hr[1024 + kk]);
        float h1 = __bfloat162float(hr[kk+1]) + __bfloat162float(hr[1024 + kk + 1]);
        a0 += h0 * W[kk * Hq + c];
        a1 += h1 * W[(kk + 1) * Hq + c];
    }
    float acc = a0 + a1;
    if (lane < 16) {
        beta[(size_t)row * Hq + c] = 1.0f / (1.0f + __expf(-acc));
    } else {
        float xv = acc + dt_bias[c];
        float sp = fmaxf(xv, 0.f) + log1pf(__expf(-fabsf(xv)));
        dec[(size_t)row * Hq + c] = __expf(-__expf(A_log[c]) * sp);
    }
}

// ---------------- fused gated RMSNorm -> bf16 [Ah|Al] --------------------------
__global__ void gated_split_kernel(const float* __restrict__ o, const float* __restrict__ w,
                                   const float* __restrict__ gate, int gstride,
                                   __nv_bfloat16* __restrict__ outb) {
    int vec = blockIdx.x * 8 + (threadIdx.x >> 5);
    int lane = threadIdx.x & 31;
    int m = vec >> 4, hh = vec & 15;
    const float4* op = (const float4*)(o + (size_t)vec * DVq);
    const float4* gp = (const float4*)(gate + (size_t)m * gstride + hh * DVq);
    float4 v = op[lane];
    float ss = v.x*v.x + v.y*v.y + v.z*v.z + v.w*v.w;
    #pragma unroll
    for (int off = 16; off; off >>= 1) ss += __shfl_xor_sync(0xffffffffu, ss, off);
    float r = rsqrtf(ss * (1.0f / DVq) + 1e-6f);
    float4 wv = ((const float4*)w)[lane];
    float4 g = gp[lane];
    float4 ov = make_float4(v.x*r*wv.x*siluf(g.x), v.y*r*wv.y*siluf(g.y),
                            v.z*r*wv.z*siluf(g.z), v.w*r*wv.w*siluf(g.w));
    ull hi, lo; split4(ov, hi, lo);
    __nv_bfloat16* rb = outb + (size_t)m * 4096 + hh * DVq + lane * 4;
    *(ull*)rb = hi;
    *(ull*)(rb + 2048) = lo;
}

// ---------------- gated delta-rule scan (unchanged) ----------------------------
#define RSTRIDE 196
__global__ void __launch_bounds__(128)
scan_kernel(const float* __restrict__ q, const float* __restrict__ k,
            const float* __restrict__ v, const float* __restrict__ dec,
            const float* __restrict__ bt, float* __restrict__ o) {
    __shared__ alignas(16) float ring[16 * RSTRIDE];
    int quarter = blockIdx.x & 3;
    int bh = blockIdx.x >> 2;
    int b = bh >> 4, h = bh & 15;
    int tid = threadIdx.x;
    int colL = tid >> 2, sub = tid & 3;
    int col = quarter * 32 + colL;

    size_t rowBase = (size_t)b * Tq;
    const float* kb = k + rowBase * Dq + h * DKq;
    const float* qb = q + rowBase * Dq + h * DKq;
    const float* vb = v + rowBase * VDq + h * DVq + quarter * 32;
    const float* db = dec + rowBase * Hq + h;
    const float* bb = bt + rowBase * Hq + h;
    float* ob = o + rowBase * VDq + h * DVq + col;

    uint32_t ringU = smem_u32(ring);

    auto fill = [&](int hf, int blk) {
        #pragma unroll
        for (int rep = 0; rep < 3; rep++) {
            int idx = tid + rep * 128;
            if (idx < 336) {
                int sid = idx / 42, slot = idx % 42;
                int t = blk * 8 + sid;
                uint32_t sb = ringU + ((hf * 8 + sid) * RSTRIDE) * 4;
                if (slot < 16) {
                    int ch = slot >> 2, i = slot & 3;
                    CP16(sb + (ch * 20 + i * 4) * 4,      kb + (size_t)t * Dq + ch * 16 + i * 4);
                } else if (slot < 32) {
                    int s2 = slot - 16, ch = s2 >> 2, i = s2 & 3;
                    CP16(sb + (80 + ch * 20 + i * 4) * 4, qb + (size_t)t * Dq + ch * 16 + i * 4);
                } else if (slot < 40) {
                    CP16(sb + (160 + (slot - 32) * 4) * 4, vb + (size_t)t * VDq + (slot - 32) * 4);
                } else if (slot == 40) {
                    CP4(sb + 192 * 4, db + (size_t)t * Hq);
                } else {
                    CP4(sb + 193 * 4, bb + (size_t)t * Hq);
                }
            }
        }
        CPCOMMIT();
    };

    ull S[8];
    #pragma unroll
    for (int p = 0; p < 8; p++) S[p] = 0ull;

    fill(0, 0);
    fill(1, 1);

    for (int blk = 0; blk < 256; blk++) {
        CPWAIT1();
        __syncthreads();
        int hf = blk & 1;
        #pragma unroll 1
        for (int j = 0; j < 8; j++) {
            const float* st = &ring[(hf * 8 + j) * RSTRIDE];
            const ull* kp = (const ull*)(st + sub * 20);
            const ull* qp = (const ull*)(st + 80 + sub * 20);
            float vt = st[160 + colL];
            float d = st[192], bet = st[193];
            ull kr[8], qr[8];
            #pragma unroll
            for (int p = 0; p < 8; p++) { kr[p] = kp[p]; qr[p] = qp[p]; }
            ull ksa = 0ull, ksb = 0ull, qsa = 0ull, qsb = 0ull, qka = 0ull, qkb = 0ull;
            #pragma unroll
            for (int p = 0; p < 8; p += 2) {
                ksa = ffma2(kr[p],   S[p],    ksa);
                ksb = ffma2(kr[p+1], S[p+1],  ksb);
                qsa = ffma2(qr[p],   S[p],    qsa);
                qsb = ffma2(qr[p+1], S[p+1],  qsb);
                qka = ffma2(qr[p],   kr[p],   qka);
                qkb = ffma2(qr[p+1], kr[p+1], qkb);
            }
            float2 f0 = unpk(ksa), f1 = unpk(ksb);
            float2 f2 = unpk(qsa), f3 = unpk(qsb);
            float2 f4 = unpk(qka), f5 = unpk(qkb);
            float ks = (f0.x + f0.y) + (f1.x + f1.y);
            float qs = (f2.x + f2.y) + (f3.x + f3.y);
            float qk = (f4.x + f4.y) + (f5.x + f5.y);
            ks += __shfl_xor_sync(0xffffffffu, ks, 1);
            qs += __shfl_xor_sync(0xffffffffu, qs, 1);
            qk += __shfl_xor_sync(0xffffffffu, qk, 1);
            ks += __shfl_xor_sync(0xffffffffu, ks, 2);
            qs += __shfl_xor_sync(0xffffffffu, qs, 2);
            qk += __shfl_xor_sync(0xffffffffu, qk, 2);
            float vp = d * ks;
            float u = bet * (vt - vp);
            float ot = d * qs + qk * u;
            ull up = dup2(u), dpk = dup2(d);
            #pragma unroll
            for (int p = 0; p < 8; p++)
                S[p] = ffma2(kr[p], up, mul2(S[p], dpk));
            if (sub == 0) ob[(size_t)(blk * 8 + j) * VDq] = ot;
        }
        __syncthreads();
        if (blk + 2 < 256) fill(hf, blk + 2);
        else CPCOMMIT();
    }
}

// ---------------- host orchestration -----------------------------------------
static inline void launch_gemm(const __nv_bfloat16* A, const __nv_bfloat16* B,
                               const float* R, float* C, int N, int S1, int ld, int addR) {
    dim3 grid(N / 256, Mq / 128);
    gemm_tc<<<grid, 256, GSMEM>>>(A, B, R, C, N, S1, ld, addR);
}

extern "C" void kernel_launch(void* const* d_in, const int* in_sizes, int n_in,
                              void* d_out, int out_size) {
    const float* hidden   = (const float*)d_in[0];
    const float* norm_w   = (const float*)d_in[1];
    const float* q_w      = (const float*)d_in[2];
    const float* k_w      = (const float*)d_in[3];
    const float* v_w      = (const float*)d_in[4];
    const float* b_w      = (const float*)d_in[5];
    const float* a_w      = (const float*)d_in[6];
    const float* A_log    = (const float*)d_in[7];
    const float* dt_bias  = (const float*)d_in[8];
    const float* conv_q_w = (const float*)d_in[9];
    const float* conv_k_w = (const float*)d_in[10];
    const float* conv_v_w = (const float*)d_in[11];
    const float* g_wm     = (const float*)d_in[12];
    const float* o_norm_w = (const float*)d_in[13];
    const float* o_w      = (const float*)d_in[14];
    const float* post_w   = (const float*)d_in[15];
    const float* gate_w   = (const float*)d_in[16];
    const float* up_w     = (const float*)d_in[17];
    const float* down_w   = (const float*)d_in[18];
    float* out = (float*)d_out;

    float *p_qkvg, *p_q, *p_k, *p_v, *p_bt, *p_gd, *p_o, *p_x, *p_gu;
    __nv_bfloat16 *p_A, *p_Bqkvg, *p_Bo, *p_Bmlp, *p_Bdwn;
    cudaGetSymbolAddress((void**)&p_qkvg, g_qkvg);
    cudaGetSymbolAddress((void**)&p_q, g_q);
    cudaGetSymbolAddress((void**)&p_k, g_k);
    cudaGetSymbolAddress((void**)&p_v, g_v);
    cudaGetSymbolAddress((void**)&p_bt, g_bt);
    cudaGetSymbolAddress((void**)&p_gd, g_gd);
    cudaGetSymbolAddress((void**)&p_o, g_o);
    cudaGetSymbolAddress((void**)&p_x, g_x);
    cudaGetSymbolAddress((void**)&p_gu, g_gu);
    cudaGetSymbolAddress((void**)&p_A, g_Aexp);
    cudaGetSymbolAddress((void**)&p_Bqkvg, g_Bqkvg);
    cudaGetSymbolAddress((void**)&p_Bo, g_Bo);
    cudaGetSymbolAddress((void**)&p_Bmlp, g_Bmlp);
    cudaGetSymbolAddress((void**)&p_Bdwn, g_Bdwn);

    cudaFuncSetAttribute(gemm_tc, cudaFuncAttributeMaxDynamicSharedMemorySize, GSMEM);

    // weight conversion: one combined launch, [Bh|Bl] layout
    SJobs jobs;
    auto setjob = [&](int j, const float* s, __nv_bfloat16* d, int K, int N) {
        jobs.src[j] = s; jobs.dst[j] = d; jobs.K[j] = K; jobs.N[j] = N;
        jobs.nx[j] = N / 32; jobs.blocks[j] = (N / 32) * (K / 32);
    };
    setjob(0, q_w,    p_Bqkvg,                        1024, 1024);
    setjob(1, k_w,    p_Bqkvg + (size_t)1024 * 2048,  1024, 1024);
    setjob(2, v_w,    p_Bqkvg + (size_t)2048 * 2048,  1024, 2048);
    setjob(3, g_wm,   p_Bqkvg + (size_t)4096 * 2048,  1024, 2048);
    setjob(4, o_w,    p_Bo,                           2048, 1024);
    setjob(5, gate_w, p_Bmlp,                         1024, 2752);
    setjob(6, up_w,   p_Bmlp + (size_t)2752 * 2048,   1024, 2752);
    setjob(7, down_w, p_Bdwn,                         2752, 1024);
    int total_blocks = 0;
    for (int j = 0; j < 8; j++) total_blocks += jobs.blocks[j];
    splitT_all<<<total_blocks, dim3(32, 8)>>>(jobs);
    cudaMemsetAsync(p_Bmlp + (size_t)5504 * 2048, 0, (size_t)128 * 2048 * sizeof(__nv_bfloat16));

    // 1) pre-norm -> bf16 [Ah|Al]; ba reads the bf16 pair
    rmsnorm_split_kernel<<<Mq, 256>>>(hidden, norm_w, p_A);
    ba_kernel<<<Mq / 4, 128>>>(p_A, b_w, a_w, A_log, dt_bias, p_bt, p_gd);

    // 2) fused q|k|v|gate projection (N=6144, K=1024 -> S1=16, ld=2048)
    launch_gemm(p_A, p_Bqkvg, nullptr, p_qkvg, 6144, 16, 2048, 0);

    // 3) conv+silu(+l2norm) for q and k (one launch), conv+silu for v
    conv_l2_kernel<<<dim3((Mq * Hq) / 8, 2), 256>>>(p_qkvg, 6144, conv_q_w, conv_k_w, p_q, p_k);
    conv_silu_kernel<<<(int)(((size_t)Mq * 2048 + 255) / 256), 256>>>(p_qkvg + 2048, 6144, conv_v_w, p_v, 2048);

    // 4) scan
    scan_kernel<<<Bq * Hq * 4, 128>>>(p_q, p_k, p_v, p_gd, p_bt, p_o);

    // 5) gated per-head RMSNorm -> bf16 [Ah|Al] (width 4096)
    gated_split_kernel<<<(Mq * Hq) / 8, 256>>>(p_o, o_norm_w, p_qkvg + 4096, 6144, p_A);

    // 6) output projection + residual (K=2048 -> S1=32, ld=4096)
    launch_gemm(p_A, p_Bo, hidden, p_x, 1024, 32, 4096, 1);

    // 7) post norm -> bf16 [Ah|Al]
    rmsnorm_split_kernel<<<Mq, 256>>>(p_x, post_w, p_A);

    // 8) MLP (K=1024 -> S1=16; down K=2752 -> S1=43, ld=5504)
    launch_gemm(p_A, p_Bmlp, nullptr, p_gu, FFp, 16, 2048, 0);
    act_split<<<(int)(((size_t)Mq * FFq + 255) / 256), 256>>>(p_gu, p_A);
    launch_gemm(p_A, p_Bdwn, p_x, out, 1024, 43, 5504, 1);
}